// round 15
// baseline (speedup 1.0000x reference)
#include <cuda_runtime.h>
#include <cuda_fp16.h>
#include <stdint.h>

#define N 4096
#define D1 512
#define D2H 1024
#define KNN 10
#define MASKW (N / 64)
#define BM 128
#define NTILES (N / BM)                    // 32
#define NBLK ((NTILES * (NTILES + 1)) / 2) // 528
#define CSTR 129                           // smem C tile stride (floats)
#define STAGE_B 32768
#define DYN_SMEM (3 * STAGE_B)             // 98304: 3 stages of (A 16K + B 16K)
#define NTHR 512

// ---------------- scratch (device globals; no allocation allowed) ----------
__device__ __align__(16) float g_d2[(size_t)N * N];        // 64 MB
__device__ __align__(16) float g_tmin[(size_t)N * NTILES]; // per-(row,tile) min
__device__ unsigned long long g_mask[(size_t)N * MASKW];   // 2 MB
__device__ int g_asum;
__device__ float g_sq[N];
__device__ float g_rn[N];
__device__ __align__(16) __half g_ahi[(size_t)N * D1];
__device__ __align__(16) __half g_alo[(size_t)N * D1];
__device__ __align__(16) __half g_bhi[(size_t)N * D2H];

// ---------------- helpers ----------------------------------------------------
__device__ __forceinline__ uint32_t smem_u32(const void* p) {
    uint32_t a;
    asm("{ .reg .u64 t; cvta.to.shared.u64 t, %1; cvt.u32.u64 %0, t; }" : "=r"(a) : "l"(p));
    return a;
}
#define SWZ(x) ((uint32_t)(x) ^ ((((uint32_t)(x)) >> 3) & 0x70))

__device__ __forceinline__ void cp16(uint32_t s, const void* g) {
    asm volatile("cp.async.cg.shared.global [%0], [%1], 16;" :: "r"(s), "l"(g));
}
#define CP_COMMIT() asm volatile("cp.async.commit_group;" ::: "memory")
#define CP_WAIT0() asm volatile("cp.async.wait_group 0;" ::: "memory")
#define CP_WAIT1() asm volatile("cp.async.wait_group 1;" ::: "memory")

__device__ __forceinline__ void ldsm4(uint32_t& r0, uint32_t& r1, uint32_t& r2, uint32_t& r3,
                                      uint32_t addr) {
    asm volatile("ldmatrix.sync.aligned.m8n8.x4.shared.b16 {%0,%1,%2,%3}, [%4];"
                 : "=r"(r0), "=r"(r1), "=r"(r2), "=r"(r3) : "r"(addr));
}
__device__ __forceinline__ void mma16816(float c[4], const uint32_t a[4],
                                         uint32_t b0, uint32_t b1) {
    asm volatile("mma.sync.aligned.m16n8k16.row.col.f32.f16.f16.f32 "
                 "{%0,%1,%2,%3}, {%4,%5,%6,%7}, {%8,%9}, {%0,%1,%2,%3};"
                 : "+f"(c[0]), "+f"(c[1]), "+f"(c[2]), "+f"(c[3])
                 : "r"(a[0]), "r"(a[1]), "r"(a[2]), "r"(a[3]), "r"(b0), "r"(b1));
}

__device__ __forceinline__ void tri_map(int t, int& bi, int& bj) {
    int i = 0, rem = t, span = NTILES;
    while (rem >= span) { rem -= span; i++; span--; }
    bi = i;
    bj = i + rem;
}

// ---------------- prep: split + rowstats + mask zero (fused) -------------------
__global__ __launch_bounds__(256) void k_prep(const float* __restrict__ orig,
                                              const float* __restrict__ hid) {
    g_mask[blockIdx.x * 256 + threadIdx.x] = 0ull;
    if (blockIdx.x == 0 && threadIdx.x == 0) g_asum = 0;

    int w = blockIdx.x * 8 + (threadIdx.x >> 5);
    int lane = threadIdx.x & 31;
    if (w < N) {
        const float4* src = (const float4*)(orig + (size_t)w * D1);
        uint2* dhi = (uint2*)(g_ahi + (size_t)w * D1);
        uint2* dlo = (uint2*)(g_alo + (size_t)w * D1);
        float s = 0.f;
        #pragma unroll
        for (int ch = 0; ch < D1 / 128; ch++) {
            int c = lane + ch * 32;
            float4 v = src[c];
            s += v.x * v.x + v.y * v.y + v.z * v.z + v.w * v.w;
            __half hx = __float2half_rn(v.x), hy = __float2half_rn(v.y);
            __half hz = __float2half_rn(v.z), hw = __float2half_rn(v.w);
            __half2 h0 = {hx, hy}, h1 = {hz, hw};
            __half2 l0 = {__float2half_rn(v.x - __half2float(hx)),
                          __float2half_rn(v.y - __half2float(hy))};
            __half2 l1 = {__float2half_rn(v.z - __half2float(hz)),
                          __float2half_rn(v.w - __half2float(hw))};
            dhi[c] = make_uint2(*(uint32_t*)&h0, *(uint32_t*)&h1);
            dlo[c] = make_uint2(*(uint32_t*)&l0, *(uint32_t*)&l1);
        }
        #pragma unroll
        for (int o = 16; o; o >>= 1) s += __shfl_down_sync(0xFFFFFFFFu, s, o);
        if (lane == 0) g_sq[w] = s;
    } else {
        int r = w - N;
        const float4* src = (const float4*)(hid + (size_t)r * D2H);
        uint2* dhi = (uint2*)(g_bhi + (size_t)r * D2H);
        float s = 0.f;
        #pragma unroll
        for (int ch = 0; ch < D2H / 128; ch++) {
            int c = lane + ch * 32;
            float4 v = src[c];
            s += v.x * v.x + v.y * v.y + v.z * v.z + v.w * v.w;
            __half2 h0 = {__float2half_rn(v.x), __float2half_rn(v.y)};
            __half2 h1 = {__float2half_rn(v.z), __float2half_rn(v.w)};
            dhi[c] = make_uint2(*(uint32_t*)&h0, *(uint32_t*)&h1);
        }
        #pragma unroll
        for (int o = 16; o; o >>= 1) s += __shfl_down_sync(0xFFFFFFFFu, s, o);
        if (lane == 0) g_rn[r] = 1.0f / fmaxf(sqrtf(s), 1e-12f);
    }
}

// ---------------- HMMA mainloop: 512 thr, 16 warps (4Mx4N), 32x32 warp tiles ----
// 3-stage cp.async, 1 barrier/chunk. NSEG==3: seg0 hi*hi, seg1 hi*lo, seg2 lo*hi.
// NSEG==1: hi*hi only.
template <int KSRC, int NSEG>
__device__ __forceinline__ void mma_mainloop(const __half* __restrict__ hi,
                                             const __half* __restrict__ lo,
                                             int i0, int j0, uint32_t sbase,
                                             float acc[2][4][4]) {
    const int tid = threadIdx.x;
    const int lane = tid & 31, wid = tid >> 5;
    const int wm = wid & 3, wn = wid >> 2;
    const int grp = lane >> 3, lr = lane & 7;
    const int NCH = (NSEG * KSRC) / 64;

    int rows[2], cols[2];
    #pragma unroll
    for (int t = 0; t < 2; t++) {
        int c = tid + t * NTHR;
        rows[t] = c >> 3;
        cols[t] = (c & 7) * 8;
    }

    auto issue = [&](int kc, int st) {
        int gk = kc * 64;
        int seg = gk / KSRC;
        int kk = gk - seg * KSRC;
        const __half* sa;
        const __half* sb;
        if (NSEG == 1) {
            sa = hi; sb = hi;
        } else {
            sa = (seg == 2) ? lo : hi;
            sb = (seg == 1) ? lo : hi;
        }
        uint32_t ab = sbase + st * STAGE_B;
        uint32_t bb = ab + 16384;
        #pragma unroll
        for (int t = 0; t < 2; t++) {
            uint32_t sw = SWZ(rows[t] * 128 + cols[t] * 2);
            cp16(ab + sw, sa + (size_t)(i0 + rows[t]) * KSRC + kk + cols[t]);
            cp16(bb + sw, sb + (size_t)(j0 + rows[t]) * KSRC + kk + cols[t]);
        }
        CP_COMMIT();
    };

    issue(0, 0);
    issue(1, 1);
    int st = 0;
    for (int kc = 0; kc < NCH; kc++) {
        if (kc + 1 < NCH) CP_WAIT1(); else CP_WAIT0();
        __syncthreads();
        if (kc + 2 < NCH) {
            int st2 = st + 2; if (st2 >= 3) st2 -= 3;
            issue(kc + 2, st2);
        }
        uint32_t ab = sbase + st * STAGE_B;
        uint32_t bb = ab + 16384;
        #pragma unroll
        for (int ks = 0; ks < 4; ks++) {
            uint32_t a[2][4], b[2][4];
            #pragma unroll
            for (int mi = 0; mi < 2; mi++) {
                int mrow = wm * 32 + mi * 16 + (grp & 1) * 8 + lr;
                uint32_t addr = ab + SWZ(mrow * 128 + ks * 32 + (grp >> 1) * 16);
                ldsm4(a[mi][0], a[mi][1], a[mi][2], a[mi][3], addr);
            }
            #pragma unroll
            for (int nb = 0; nb < 2; nb++) {
                int nrow = wn * 32 + nb * 16 + (grp & 1) * 8 + lr;
                uint32_t addr = bb + SWZ(nrow * 128 + ks * 32 + (grp >> 1) * 16);
                ldsm4(b[nb][0], b[nb][1], b[nb][2], b[nb][3], addr);
            }
            #pragma unroll
            for (int mi = 0; mi < 2; mi++)
                #pragma unroll
                for (int ni = 0; ni < 4; ni++) {
                    int nb = ni >> 1, h = ni & 1;
                    mma16816(acc[mi][ni], a[mi], b[nb][h], b[nb][h + 2]);
                }
        }
        if (++st == 3) st = 0;
    }
    __syncthreads();
}

__device__ __forceinline__ void stage_c(float* cs, float acc[2][4][4]) {
    const int lane = threadIdx.x & 31, wid = threadIdx.x >> 5;
    const int wm = wid & 3, wn = wid >> 2;
    #pragma unroll
    for (int mi = 0; mi < 2; mi++)
        #pragma unroll
        for (int ni = 0; ni < 4; ni++) {
            int r0 = wm * 32 + mi * 16 + (lane >> 2);
            int c0 = wn * 32 + ni * 8 + (lane & 3) * 2;
            cs[r0 * CSTR + c0] = acc[mi][ni][0];
            cs[r0 * CSTR + c0 + 1] = acc[mi][ni][1];
            cs[(r0 + 8) * CSTR + c0] = acc[mi][ni][2];
            cs[(r0 + 8) * CSTR + c0 + 1] = acc[mi][ni][3];
        }
}

// ---------------- GEMM 1: d2 (fp16 3-seg) + per-(row,tile) minima --------------
__global__ __launch_bounds__(NTHR, 2) void k_gemm_d2_mma() {
    extern __shared__ char dsm[];
    __shared__ float srow[128], scol[128];
    __shared__ float cm4[4][128];
    const int tid = threadIdx.x;
    int bi, bj;
    tri_map(blockIdx.x, bi, bj);
    int i0 = bi * BM, j0 = bj * BM;
    uint32_t sbase = smem_u32(dsm);

    float acc[2][4][4];
    #pragma unroll
    for (int a = 0; a < 2; a++)
        #pragma unroll
        for (int b = 0; b < 4; b++)
            #pragma unroll
            for (int c = 0; c < 4; c++) acc[a][b][c] = 0.f;

    mma_mainloop<D1, 3>(g_ahi, g_alo, i0, j0, sbase, acc);

    float* cs = (float*)dsm;
    stage_c(cs, acc);
    if (tid < 128) { srow[tid] = g_sq[i0 + tid]; scol[tid] = g_sq[j0 + tid]; }
    __syncthreads();

    const int c = tid & 127, rg = tid >> 7; // fixed col, 4 row-groups
    // direct tile: thread scans rows 4t+rg, fixed j-col c
    float m1 = 3.4e38f;
    #pragma unroll 4
    for (int t = 0; t < 32; t++) {
        int r = t * 4 + rg;
        float d2 = fmaxf(srow[r] + scol[c] - 2.0f * cs[r * CSTR + c], 0.0f);
        m1 = fminf(m1, d2);
        g_d2[(size_t)(i0 + r) * N + j0 + c] = d2;
    }
    cm4[rg][c] = m1;
    __syncthreads();
    if (tid < 128) {
        float mm = fminf(fminf(cm4[0][tid], cm4[1][tid]),
                         fminf(cm4[2][tid], cm4[3][tid]));
        g_tmin[(size_t)(j0 + tid) * NTILES + bi] = mm; // min over i-rows
    }

    if (bi != bj) {
        // mirror tile: thread scans j-rows 4t+rg, fixed i-col c
        float m2 = 3.4e38f;
        #pragma unroll 4
        for (int t = 0; t < 32; t++) {
            int r = t * 4 + rg;
            float d2 = fmaxf(srow[c] + scol[r] - 2.0f * cs[c * CSTR + r], 0.0f);
            m2 = fminf(m2, d2);
            g_d2[(size_t)(j0 + r) * N + i0 + c] = d2;
        }
        __syncthreads();
        cm4[rg][c] = m2;
        __syncthreads();
        if (tid < 128) {
            float mm = fminf(fminf(cm4[0][tid], cm4[1][tid]),
                             fminf(cm4[2][tid], cm4[3][tid]));
            g_tmin[(size_t)(i0 + tid) * NTILES + bj] = mm; // min over j-rows
        }
    }
}

// ---------------- GEMM 2: cosine + masks + both planes (fp16 single) -----------
__global__ __launch_bounds__(NTHR, 2) void k_gemm_out_mma(float* __restrict__ out) {
    extern __shared__ char dsm[];
    __shared__ float rrow[128], rcol[128];
    __shared__ unsigned long long mr[128][2];
    const int tid = threadIdx.x;
    int bi, bj;
    tri_map(blockIdx.x, bi, bj);
    int i0 = bi * BM, j0 = bj * BM;
    uint32_t sbase = smem_u32(dsm);

    float acc[2][4][4];
    #pragma unroll
    for (int a = 0; a < 2; a++)
        #pragma unroll
        for (int b = 0; b < 4; b++)
            #pragma unroll
            for (int c = 0; c < 4; c++) acc[a][b][c] = 0.f;

    mma_mainloop<D2H, 1>(g_bhi, g_bhi, i0, j0, sbase, acc);

    float* cs = (float*)dsm;
    stage_c(cs, acc);
    if (tid < 128) { rrow[tid] = g_rn[i0 + tid]; rcol[tid] = g_rn[j0 + tid]; }
    if (tid < 256)
        mr[tid >> 1][tid & 1] =
            g_mask[(size_t)(i0 + (tid >> 1)) * MASKW + (j0 >> 6) + (tid & 1)];
    __syncthreads();

    float asum = (float)g_asum;
    float Nw = 0.5f / asum;
    float Nb = 1.0f / ((float)N * (float)N - 2.0f * asum);
    const size_t NN = (size_t)N * N;
    const int c = tid & 127, rg = tid >> 7;

    #pragma unroll 4
    for (int t = 0; t < 32; t++) {
        int r = t * 4 + rg;
        float C = cs[r * CSTR + c] * rrow[r] * rcol[c];
        unsigned a = (unsigned)((mr[r][c >> 6] >> (c & 63)) & 1ull);
        size_t o = (size_t)(i0 + r) * N + j0 + c;
        out[o] = a ? 0.0f : Nb * C;
        out[NN + o] = a ? Nw * C : 0.0f;
    }
    if (bi != bj) {
        #pragma unroll 4
        for (int t = 0; t < 32; t++) {
            int r = t * 4 + rg;
            float C = cs[c * CSTR + r] * rrow[c] * rcol[r];
            unsigned a = (unsigned)((mr[c][r >> 6] >> (r & 63)) & 1ull);
            size_t o = (size_t)(j0 + r) * N + i0 + c;
            out[o] = a ? 0.0f : Nb * C;
            out[NN + o] = a ? Nw * C : 0.0f;
        }
    }
}

// ---------------- kNN: tile-minima threshold + sparse scan + fused count -------
__global__ __launch_bounds__(128) void k_knn() {
    int row = blockIdx.x, tid = threadIdx.x;
    __shared__ float shT;
    __shared__ unsigned shMask;
    __shared__ int cnt;
    __shared__ unsigned long long cand[1024];
    if (tid == 0) cnt = 0;

    if (tid < 32) {
        float tm = g_tmin[(size_t)row * NTILES + tid];
        int rank = 0;
        #pragma unroll
        for (int j = 0; j < 32; j++) {
            float vj = __shfl_sync(0xFFFFFFFFu, tm, j);
            rank += (vj < tm) || (vj == tm && j < tid);
        }
        unsigned bal = __ballot_sync(0xFFFFFFFFu, rank == KNN - 1);
        int src = __ffs(bal) - 1;
        float T = __shfl_sync(0xFFFFFFFFu, tm, src); // 10th smallest tile-min
        unsigned msk = __ballot_sync(0xFFFFFFFFu, tm <= T);
        if (tid == 0) { shT = T; shMask = msk; }
    }
    __syncthreads();

    float T = shT;
    unsigned msk = shMask;
    const float* dr = g_d2 + (size_t)row * N;
    while (msk) {
        int b = __ffs(msk) - 1;
        msk &= msk - 1;
        float v = dr[b * 128 + tid];
        if (v <= T) {
            int p = atomicAdd(&cnt, 1);
            if (p < 1024)
                cand[p] = ((unsigned long long)__float_as_uint(v) << 32)
                        | (unsigned)(b * 128 + tid);
        }
    }
    __syncthreads();

    if (tid == 0) {
        int m = cnt < 1024 ? cnt : 1024;
        int newbits = 0;
        for (int t = 0; t < KNN; t++) {
            int best = t;
            for (int u = t + 1; u < m; u++)
                if (cand[u] < cand[best]) best = u;
            unsigned long long tmp = cand[best];
            cand[best] = cand[t]; cand[t] = tmp;
            unsigned j = (unsigned)tmp;
            unsigned long long b1 = 1ull << (j & 63);
            unsigned long long b2 = 1ull << (row & 63);
            unsigned long long o1 = atomicOr(&g_mask[(size_t)row * MASKW + (j >> 6)], b1);
            unsigned long long o2 = atomicOr(&g_mask[(size_t)j * MASKW + (row >> 6)], b2);
            newbits += !(o1 & b1);
            newbits += !(o2 & b2);
        }
        if (newbits) atomicAdd(&g_asum, newbits);
    }
}

// ---------------------------------------------------------------------------
extern "C" void kernel_launch(void* const* d_in, const int* in_sizes, int n_in,
                              void* d_out, int out_size) {
    const float* orig = (const float*)d_in[0]; // [4096, 512]
    const float* hid  = (const float*)d_in[1]; // [4096, 1024]
    float* out = (float*)d_out;                // [2, 4096, 4096]

    cudaFuncSetAttribute(k_gemm_d2_mma, cudaFuncAttributeMaxDynamicSharedMemorySize, DYN_SMEM);
    cudaFuncSetAttribute(k_gemm_out_mma, cudaFuncAttributeMaxDynamicSharedMemorySize, DYN_SMEM);

    k_prep<<<1024, 256>>>(orig, hid);
    k_gemm_d2_mma<<<NBLK, NTHR, DYN_SMEM>>>();
    k_knn<<<N, 128>>>();
    k_gemm_out_mma<<<NBLK, NTHR, DYN_SMEM>>>(out);
}

// round 16
// speedup vs baseline: 1.1449x; 1.1449x over previous
#include <cuda_runtime.h>
#include <cuda_fp16.h>
#include <stdint.h>

#define N 4096
#define D1 512
#define D2H 1024
#define KNN 10
#define MASKW (N / 64)
#define BM 128
#define NTILES (N / BM)                    // 32
#define NBLK ((NTILES * (NTILES + 1)) / 2) // 528
#define CSTR 129                           // smem C tile stride (floats)
#define STAGE_B 32768
#define DYN_SMEM (3 * STAGE_B)             // 98304: 3 stages of (A 16K + B 16K)

// ---------------- scratch (device globals; no allocation allowed) ----------
__device__ __align__(16) float g_d2[(size_t)N * N];        // 64 MB
__device__ __align__(16) float g_tmin[(size_t)N * NTILES]; // per-(row,tile) min
__device__ unsigned long long g_mask[(size_t)N * MASKW];   // 2 MB
__device__ int g_asum;
__device__ float g_sq[N];
__device__ float g_rn[N];
__device__ __align__(16) __half g_ahi[(size_t)N * D1];
__device__ __align__(16) __half g_alo[(size_t)N * D1];
__device__ __align__(16) __half g_bhi[(size_t)N * D2H];

// ---------------- helpers ----------------------------------------------------
__device__ __forceinline__ uint32_t smem_u32(const void* p) {
    uint32_t a;
    asm("{ .reg .u64 t; cvta.to.shared.u64 t, %1; cvt.u32.u64 %0, t; }" : "=r"(a) : "l"(p));
    return a;
}
#define SWZ(x) ((uint32_t)(x) ^ ((((uint32_t)(x)) >> 3) & 0x70))

__device__ __forceinline__ void cp16(uint32_t s, const void* g) {
    asm volatile("cp.async.cg.shared.global [%0], [%1], 16;" :: "r"(s), "l"(g));
}
#define CP_COMMIT() asm volatile("cp.async.commit_group;" ::: "memory")
#define CP_WAIT0() asm volatile("cp.async.wait_group 0;" ::: "memory")
#define CP_WAIT1() asm volatile("cp.async.wait_group 1;" ::: "memory")

__device__ __forceinline__ void ldsm4(uint32_t& r0, uint32_t& r1, uint32_t& r2, uint32_t& r3,
                                      uint32_t addr) {
    asm volatile("ldmatrix.sync.aligned.m8n8.x4.shared.b16 {%0,%1,%2,%3}, [%4];"
                 : "=r"(r0), "=r"(r1), "=r"(r2), "=r"(r3) : "r"(addr));
}
__device__ __forceinline__ void mma16816(float c[4], const uint32_t a[4],
                                         uint32_t b0, uint32_t b1) {
    asm volatile("mma.sync.aligned.m16n8k16.row.col.f32.f16.f16.f32 "
                 "{%0,%1,%2,%3}, {%4,%5,%6,%7}, {%8,%9}, {%0,%1,%2,%3};"
                 : "+f"(c[0]), "+f"(c[1]), "+f"(c[2]), "+f"(c[3])
                 : "r"(a[0]), "r"(a[1]), "r"(a[2]), "r"(a[3]), "r"(b0), "r"(b1));
}

__device__ __forceinline__ void tri_map(int t, int& bi, int& bj) {
    int i = 0, rem = t, span = NTILES;
    while (rem >= span) { rem -= span; i++; span--; }
    bi = i;
    bj = i + rem;
}

// ---------------- prep: split + rowstats + mask zero (fused) -------------------
__global__ __launch_bounds__(256) void k_prep(const float* __restrict__ orig,
                                              const float* __restrict__ hid) {
    g_mask[blockIdx.x * 256 + threadIdx.x] = 0ull;
    if (blockIdx.x == 0 && threadIdx.x == 0) g_asum = 0;

    int w = blockIdx.x * 8 + (threadIdx.x >> 5);
    int lane = threadIdx.x & 31;
    if (w < N) {
        const float4* src = (const float4*)(orig + (size_t)w * D1);
        uint2* dhi = (uint2*)(g_ahi + (size_t)w * D1);
        uint2* dlo = (uint2*)(g_alo + (size_t)w * D1);
        float s = 0.f;
        #pragma unroll
        for (int ch = 0; ch < D1 / 128; ch++) {
            int c = lane + ch * 32;
            float4 v = src[c];
            s += v.x * v.x + v.y * v.y + v.z * v.z + v.w * v.w;
            __half hx = __float2half_rn(v.x), hy = __float2half_rn(v.y);
            __half hz = __float2half_rn(v.z), hw = __float2half_rn(v.w);
            __half2 h0 = {hx, hy}, h1 = {hz, hw};
            __half2 l0 = {__float2half_rn(v.x - __half2float(hx)),
                          __float2half_rn(v.y - __half2float(hy))};
            __half2 l1 = {__float2half_rn(v.z - __half2float(hz)),
                          __float2half_rn(v.w - __half2float(hw))};
            dhi[c] = make_uint2(*(uint32_t*)&h0, *(uint32_t*)&h1);
            dlo[c] = make_uint2(*(uint32_t*)&l0, *(uint32_t*)&l1);
        }
        #pragma unroll
        for (int o = 16; o; o >>= 1) s += __shfl_down_sync(0xFFFFFFFFu, s, o);
        if (lane == 0) g_sq[w] = s;
    } else {
        int r = w - N;
        const float4* src = (const float4*)(hid + (size_t)r * D2H);
        uint2* dhi = (uint2*)(g_bhi + (size_t)r * D2H);
        float s = 0.f;
        #pragma unroll
        for (int ch = 0; ch < D2H / 128; ch++) {
            int c = lane + ch * 32;
            float4 v = src[c];
            s += v.x * v.x + v.y * v.y + v.z * v.z + v.w * v.w;
            __half2 h0 = {__float2half_rn(v.x), __float2half_rn(v.y)};
            __half2 h1 = {__float2half_rn(v.z), __float2half_rn(v.w)};
            dhi[c] = make_uint2(*(uint32_t*)&h0, *(uint32_t*)&h1);
        }
        #pragma unroll
        for (int o = 16; o; o >>= 1) s += __shfl_down_sync(0xFFFFFFFFu, s, o);
        if (lane == 0) g_rn[r] = 1.0f / fmaxf(sqrtf(s), 1e-12f);
    }
}

// ---------------- HMMA mainloop: 3-stage cp.async, 1 barrier/chunk --------------
// NSEG==3: seg0 hi*hi, seg1 hi*lo, seg2 lo*hi (fp16 split; drops ~2^-24 lo*lo)
// NSEG==1: hi*hi only (plain fp16 GEMM)
template <int KSRC, int NSEG>
__device__ __forceinline__ void mma_mainloop(const __half* __restrict__ hi,
                                             const __half* __restrict__ lo,
                                             int i0, int j0, uint32_t sbase,
                                             float acc[2][8][4]) {
    const int tid = threadIdx.x;
    const int lane = tid & 31, wid = tid >> 5;
    const int wm = wid & 3, wn = wid >> 2;
    const int grp = lane >> 3, lr = lane & 7;
    const int NCH = (NSEG * KSRC) / 64;

    int rows[4], cols[4];
    #pragma unroll
    for (int t = 0; t < 4; t++) {
        int c = tid + t * 256;
        rows[t] = c >> 3;
        cols[t] = (c & 7) * 8;
    }

    auto issue = [&](int kc, int st) {
        int gk = kc * 64;
        int seg = gk / KSRC;
        int kk = gk - seg * KSRC;
        const __half* sa;
        const __half* sb;
        if (NSEG == 1) {
            sa = hi; sb = hi;
        } else {
            sa = (seg == 2) ? lo : hi;
            sb = (seg == 1) ? lo : hi;
        }
        uint32_t ab = sbase + st * STAGE_B;
        uint32_t bb = ab + 16384;
        #pragma unroll
        for (int t = 0; t < 4; t++) {
            uint32_t sw = SWZ(rows[t] * 128 + cols[t] * 2);
            cp16(ab + sw, sa + (size_t)(i0 + rows[t]) * KSRC + kk + cols[t]);
            cp16(bb + sw, sb + (size_t)(j0 + rows[t]) * KSRC + kk + cols[t]);
        }
        CP_COMMIT();
    };

    issue(0, 0);
    issue(1, 1);
    int st = 0;
    for (int kc = 0; kc < NCH; kc++) {
        if (kc + 1 < NCH) CP_WAIT1(); else CP_WAIT0();
        __syncthreads();
        if (kc + 2 < NCH) {
            int st2 = st + 2; if (st2 >= 3) st2 -= 3;
            issue(kc + 2, st2);
        }
        uint32_t ab = sbase + st * STAGE_B;
        uint32_t bb = ab + 16384;
        #pragma unroll
        for (int ks = 0; ks < 4; ks++) {
            uint32_t a[2][4], b[4][4];
            #pragma unroll
            for (int mi = 0; mi < 2; mi++) {
                int mrow = wm * 32 + mi * 16 + (grp & 1) * 8 + lr;
                uint32_t addr = ab + SWZ(mrow * 128 + ks * 32 + (grp >> 1) * 16);
                ldsm4(a[mi][0], a[mi][1], a[mi][2], a[mi][3], addr);
            }
            #pragma unroll
            for (int nb = 0; nb < 4; nb++) {
                int nrow = wn * 64 + nb * 16 + (grp & 1) * 8 + lr;
                uint32_t addr = bb + SWZ(nrow * 128 + ks * 32 + (grp >> 1) * 16);
                ldsm4(b[nb][0], b[nb][1], b[nb][2], b[nb][3], addr);
            }
            #pragma unroll
            for (int mi = 0; mi < 2; mi++)
                #pragma unroll
                for (int ni = 0; ni < 8; ni++) {
                    int nb = ni >> 1, h = ni & 1;
                    mma16816(acc[mi][ni], a[mi], b[nb][h], b[nb][h + 2]);
                }
        }
        if (++st == 3) st = 0;
    }
    __syncthreads();
}

__device__ __forceinline__ void stage_c(float* cs, float acc[2][8][4]) {
    const int lane = threadIdx.x & 31, wid = threadIdx.x >> 5;
    const int wm = wid & 3, wn = wid >> 2;
    #pragma unroll
    for (int mi = 0; mi < 2; mi++)
        #pragma unroll
        for (int ni = 0; ni < 8; ni++) {
            int r0 = wm * 32 + mi * 16 + (lane >> 2);
            int c0 = wn * 64 + ni * 8 + (lane & 3) * 2;
            cs[r0 * CSTR + c0] = acc[mi][ni][0];
            cs[r0 * CSTR + c0 + 1] = acc[mi][ni][1];
            cs[(r0 + 8) * CSTR + c0] = acc[mi][ni][2];
            cs[(r0 + 8) * CSTR + c0 + 1] = acc[mi][ni][3];
        }
}

// ---------------- GEMM 1: d2 (fp16 3-seg) + per-(row,tile) minima --------------
__global__ __launch_bounds__(256, 2) void k_gemm_d2_mma() {
    extern __shared__ char dsm[];
    __shared__ float srow[128], scol[128];
    __shared__ float cmin[128];
    const int tid = threadIdx.x;
    int bi, bj;
    tri_map(blockIdx.x, bi, bj);
    int i0 = bi * BM, j0 = bj * BM;
    uint32_t sbase = smem_u32(dsm);

    float acc[2][8][4];
    #pragma unroll
    for (int a = 0; a < 2; a++)
        #pragma unroll
        for (int b = 0; b < 8; b++)
            #pragma unroll
            for (int c = 0; c < 4; c++) acc[a][b][c] = 0.f;

    mma_mainloop<D1, 3>(g_ahi, g_alo, i0, j0, sbase, acc);

    float* cs = (float*)dsm;
    stage_c(cs, acc);
    if (tid < 128) { srow[tid] = g_sq[i0 + tid]; scol[tid] = g_sq[j0 + tid]; }
    __syncthreads();

    // direct tile: thread has fixed j-col (tid&127), scans 64 i-rows
    float m1 = 3.4e38f;
    #pragma unroll 4
    for (int t = 0; t < 64; t++) {
        int e = t * 256 + tid;
        int r = e >> 7, c = e & 127;
        float d2 = fmaxf(srow[r] + scol[c] - 2.0f * cs[r * CSTR + c], 0.0f);
        m1 = fminf(m1, d2);
        __stcs(&g_d2[(size_t)(i0 + r) * N + j0 + c], d2);
    }
    if (tid < 128) cmin[tid] = m1;
    __syncthreads();
    if (tid >= 128) cmin[tid - 128] = fminf(cmin[tid - 128], m1);
    __syncthreads();
    if (tid < 128) g_tmin[(size_t)(j0 + tid) * NTILES + bi] = cmin[tid];

    if (bi != bj) {
        // mirror tile: thread has fixed i-col (tid&127), scans 64 j-rows
        float m2 = 3.4e38f;
        #pragma unroll 4
        for (int t = 0; t < 64; t++) {
            int e = t * 256 + tid;
            int r = e >> 7, c = e & 127;
            float d2 = fmaxf(srow[c] + scol[r] - 2.0f * cs[c * CSTR + r], 0.0f);
            m2 = fminf(m2, d2);
            __stcs(&g_d2[(size_t)(j0 + r) * N + i0 + c], d2);
        }
        __syncthreads();
        if (tid < 128) cmin[tid] = m2;
        __syncthreads();
        if (tid >= 128) cmin[tid - 128] = fminf(cmin[tid - 128], m2);
        __syncthreads();
        if (tid < 128) g_tmin[(size_t)(i0 + tid) * NTILES + bj] = cmin[tid];
    }
}

// ---------------- GEMM 2: cosine + masks + both planes (fp16 single) -----------
__global__ __launch_bounds__(256, 2) void k_gemm_out_mma(float* __restrict__ out) {
    extern __shared__ char dsm[];
    __shared__ float rrow[128], rcol[128];
    __shared__ unsigned long long mr[128][2];
    const int tid = threadIdx.x;
    int bi, bj;
    tri_map(blockIdx.x, bi, bj);
    int i0 = bi * BM, j0 = bj * BM;
    uint32_t sbase = smem_u32(dsm);

    float acc[2][8][4];
    #pragma unroll
    for (int a = 0; a < 2; a++)
        #pragma unroll
        for (int b = 0; b < 8; b++)
            #pragma unroll
            for (int c = 0; c < 4; c++) acc[a][b][c] = 0.f;

    mma_mainloop<D2H, 1>(g_bhi, g_bhi, i0, j0, sbase, acc);

    float* cs = (float*)dsm;
    stage_c(cs, acc);
    if (tid < 128) { rrow[tid] = g_rn[i0 + tid]; rcol[tid] = g_rn[j0 + tid]; }
    mr[tid >> 1][tid & 1] = g_mask[(size_t)(i0 + (tid >> 1)) * MASKW + (j0 >> 6) + (tid & 1)];
    __syncthreads();

    float asum = (float)g_asum;
    float Nw = 0.5f / asum;
    float Nb = 1.0f / ((float)N * (float)N - 2.0f * asum);
    const size_t NN = (size_t)N * N;

    #pragma unroll 4
    for (int t = 0; t < 64; t++) {
        int e = t * 256 + tid;
        int r = e >> 7, c = e & 127;
        float C = cs[r * CSTR + c] * rrow[r] * rcol[c];
        unsigned a = (unsigned)((mr[r][c >> 6] >> (c & 63)) & 1ull);
        size_t o = (size_t)(i0 + r) * N + j0 + c;
        __stcs(&out[o], a ? 0.0f : Nb * C);
        __stcs(&out[NN + o], a ? Nw * C : 0.0f);
    }
    if (bi != bj) {
        #pragma unroll 4
        for (int t = 0; t < 64; t++) {
            int e = t * 256 + tid;
            int r = e >> 7, c = e & 127;
            float C = cs[c * CSTR + r] * rrow[c] * rcol[r];
            unsigned a = (unsigned)((mr[c][r >> 6] >> (r & 63)) & 1ull);
            size_t o = (size_t)(j0 + r) * N + i0 + c;
            __stcs(&out[o], a ? 0.0f : Nb * C);
            __stcs(&out[NN + o], a ? Nw * C : 0.0f);
        }
    }
}

// ---------------- kNN: tile-minima threshold + sparse scan + fused count -------
__global__ __launch_bounds__(128) void k_knn() {
    int row = blockIdx.x, tid = threadIdx.x;
    __shared__ float shT;
    __shared__ unsigned shMask;
    __shared__ int cnt;
    __shared__ unsigned long long cand[1024];
    if (tid == 0) cnt = 0;

    if (tid < 32) {
        float tm = g_tmin[(size_t)row * NTILES + tid];
        int rank = 0;
        #pragma unroll
        for (int j = 0; j < 32; j++) {
            float vj = __shfl_sync(0xFFFFFFFFu, tm, j);
            rank += (vj < tm) || (vj == tm && j < tid);
        }
        unsigned bal = __ballot_sync(0xFFFFFFFFu, rank == KNN - 1);
        int src = __ffs(bal) - 1;
        float T = __shfl_sync(0xFFFFFFFFu, tm, src); // 10th smallest tile-min
        unsigned msk = __ballot_sync(0xFFFFFFFFu, tm <= T);
        if (tid == 0) { shT = T; shMask = msk; }
    }
    __syncthreads();

    float T = shT;
    unsigned msk = shMask;
    const float* dr = g_d2 + (size_t)row * N;
    while (msk) {
        int b = __ffs(msk) - 1;
        msk &= msk - 1;
        float v = dr[b * 128 + tid];
        if (v <= T) {
            int p = atomicAdd(&cnt, 1);
            if (p < 1024)
                cand[p] = ((unsigned long long)__float_as_uint(v) << 32)
                        | (unsigned)(b * 128 + tid);
        }
    }
    __syncthreads();

    if (tid == 0) {
        int m = cnt < 1024 ? cnt : 1024;
        int newbits = 0;
        for (int t = 0; t < KNN; t++) {
            int best = t;
            for (int u = t + 1; u < m; u++)
                if (cand[u] < cand[best]) best = u;
            unsigned long long tmp = cand[best];
            cand[best] = cand[t]; cand[t] = tmp;
            unsigned j = (unsigned)tmp;
            unsigned long long b1 = 1ull << (j & 63);
            unsigned long long b2 = 1ull << (row & 63);
            unsigned long long o1 = atomicOr(&g_mask[(size_t)row * MASKW + (j >> 6)], b1);
            unsigned long long o2 = atomicOr(&g_mask[(size_t)j * MASKW + (row >> 6)], b2);
            newbits += !(o1 & b1);
            newbits += !(o2 & b2);
        }
        if (newbits) atomicAdd(&g_asum, newbits);
    }
}

// ---------------------------------------------------------------------------
extern "C" void kernel_launch(void* const* d_in, const int* in_sizes, int n_in,
                              void* d_out, int out_size) {
    const float* orig = (const float*)d_in[0]; // [4096, 512]
    const float* hid  = (const float*)d_in[1]; // [4096, 1024]
    float* out = (float*)d_out;                // [2, 4096, 4096]

    cudaFuncSetAttribute(k_gemm_d2_mma, cudaFuncAttributeMaxDynamicSharedMemorySize, DYN_SMEM);
    cudaFuncSetAttribute(k_gemm_out_mma, cudaFuncAttributeMaxDynamicSharedMemorySize, DYN_SMEM);

    k_prep<<<1024, 256>>>(orig, hid);
    k_gemm_d2_mma<<<NBLK, 256, DYN_SMEM>>>();
    k_knn<<<N, 128>>>();
    k_gemm_out_mma<<<NBLK, 256, DYN_SMEM>>>(out);
}